// round 11
// baseline (speedup 1.0000x reference)
#include <cuda_runtime.h>
#include <cuda_fp16.h>
#include <cstdint>

#define N_NODES  50000
#define N_EDGES  600000
#define BAG      16
#define VOCAB    10000
#define EMB      128
#define HID      128
#define N_GRAPHS 512
#define N_CLS    10
#define PAD_IDX  1
#define NBLK 196   // ceil(N_NODES/256)
#define COUNT_BLOCKS ((N_EDGES + 255) / 256)          // 2344

typedef unsigned long long ull;

// ---------------- scratch (static device globals; no allocation) ------------
__device__ __align__(16) __half g_x16 [N_NODES * HID];  // embed out / features
__device__ __align__(16) __half g_h16 [N_NODES * HID];  // layer1 out
__device__ __align__(16) __half g_agg16[N_NODES * HID]; // neighbor mean
__device__ __align__(16) __half g_tab16[VOCAB * EMB];   // fp16 emb table
__device__ __align__(16) float g_gsum[N_GRAPHS * HID];
__device__ __align__(16) float g_gcnt[N_GRAPHS];
// CSR
__device__ int g_degi  [N_NODES];
__device__ int g_offs  [N_NODES];
__device__ int g_cursor[N_NODES];
__device__ int g_adj   [N_EDGES];
__device__ ull g_sstate[NBLK];     // decoupled-lookback state

// ---------------- host-side streams/events (created once at load) -----------
static cudaStream_t g_s1 = nullptr;
static cudaEvent_t  g_evFork = nullptr, g_evJoin = nullptr;
namespace {
struct StreamInit {
    StreamInit() {
        cudaStreamCreateWithFlags(&g_s1, cudaStreamNonBlocking);
        cudaEventCreateWithFlags(&g_evFork, cudaEventDisableTiming);
        cudaEventCreateWithFlags(&g_evJoin, cudaEventDisableTiming);
    }
} g_stream_init;
}

// ---------------- helpers ----------------------------------------------------
__device__ __forceinline__ void red_add_v2(float* p, float a, float b) {
    asm volatile("red.global.add.v2.f32 [%0], {%1,%2};"
                 :: "l"(p), "f"(a), "f"(b) : "memory");
}
__device__ __forceinline__ void mma_f16(float* c, const uint32_t* a, const uint32_t* b) {
    asm volatile("mma.sync.aligned.m16n8k16.row.col.f32.f16.f16.f32 "
        "{%0,%1,%2,%3}, {%4,%5,%6,%7}, {%8,%9}, {%0,%1,%2,%3};"
        : "+f"(c[0]), "+f"(c[1]), "+f"(c[2]), "+f"(c[3])
        : "r"(a[0]), "r"(a[1]), "r"(a[2]), "r"(a[3]), "r"(b[0]), "r"(b[1]));
}
__device__ __forceinline__ float4 ld_h4(const __half* p) {
    uint2 u = *(const uint2*)p;
    __half2 h0 = *(__half2*)&u.x, h1 = *(__half2*)&u.y;
    float2 f0 = __half22float2(h0), f1 = __half22float2(h1);
    return make_float4(f0.x, f0.y, f1.x, f1.y);
}
__device__ __forceinline__ void st_h4(__half* p, float4 v) {
    uint2 u;
    *(__half2*)&u.x = __floats2half2_rn(v.x, v.y);
    *(__half2*)&u.y = __floats2half2_rn(v.z, v.w);
    *(uint2*)p = u;
}

// ---------------- zeroing + table prep --------------------------------------
__global__ void k_zero_pre(const float* __restrict__ table) {
    int t = blockIdx.x * blockDim.x + threadIdx.x;
    int stride = gridDim.x * blockDim.x;
    for (int i = t; i < N_NODES; i += stride) g_degi[i] = 0;
    for (int i = t; i < N_GRAPHS; i += stride) g_gcnt[i] = 0.f;
    for (int i = t; i < N_GRAPHS * HID; i += stride) g_gsum[i] = 0.f;
    for (int i = t; i < NBLK; i += stride) g_sstate[i] = 0ull;
    for (int i = t; i < VOCAB * EMB / 4; i += stride) {
        float4 v = ((const float4*)table)[i];
        st_h4(g_tab16 + i * 4, v);
    }
}

// ---------------- embedding bag (mean, pad-excluded count) ------------------
__global__ void k_embed(const int* __restrict__ tokens) {
    int w = (blockIdx.x * blockDim.x + threadIdx.x) >> 5;
    int lane = threadIdx.x & 31;
    if (w >= N_NODES) return;
    const int* tk = tokens + w * BAG;
    float4 acc = make_float4(0.f, 0.f, 0.f, 0.f);
    int cnt = 0;
#pragma unroll
    for (int t = 0; t < BAG; t++) {
        int tok = tk[t];
        if (tok != PAD_IDX) {
            cnt++;
            float4 e = ld_h4(g_tab16 + (size_t)tok * EMB + lane * 4);
            acc.x += e.x; acc.y += e.y; acc.z += e.z; acc.w += e.w;
        }
    }
    float inv = 1.0f / (float)max(cnt, 1);
    acc.x *= inv; acc.y *= inv; acc.z *= inv; acc.w *= inv;
    st_h4(g_x16 + (size_t)w * HID + lane * 4, acc);
}

// ---------------- degree (int) + graph counts -------------------------------
__global__ void k_counts(const int* __restrict__ dst, const int* __restrict__ batch) {
    int i = blockIdx.x * blockDim.x + threadIdx.x;
    if (i < N_EDGES) atomicAdd(&g_degi[dst[i]], 1);
    if (i < N_NODES) atomicAdd(&g_gcnt[batch[i]], 1.0f);
}

// ---------------- single-kernel exclusive scan (decoupled lookback) ----------
// also initializes g_cursor[i] = offs[i] for the direct fetch-and-add fill
__global__ void k_scan() {
    __shared__ int s[256];
    __shared__ ull run_sh;
    int t = threadIdx.x, bid = blockIdx.x;
    int i = bid * 256 + t;
    int v = (i < N_NODES) ? g_degi[i] : 0;
    s[t] = v; __syncthreads();
#pragma unroll
    for (int o = 1; o < 256; o <<= 1) {
        int x = (t >= o) ? s[t - o] : 0;
        __syncthreads();
        s[t] += x;
        __syncthreads();
    }
    int incl = s[t];
    int total = s[255];
    if (t == 0) {
        ull st = ((ull)(bid == 0 ? 2 : 1) << 32) | (unsigned)total;
        atomicExch(&g_sstate[bid], st);
    }
    if (t < 32) {
        ull run = 0;
        if (bid > 0) {
            int look = bid - 1;
            while (true) {
                int j = look - t;
                ull val; int stt;
                if (j >= 0) {
                    do { val = atomicAdd(&g_sstate[j], 0ull); stt = (int)(val >> 32); }
                    while (stt == 0);
                } else { val = (2ull << 32); stt = 2; }
                unsigned m = __ballot_sync(0xffffffffu, stt == 2);
                ull contrib;
                if (m) {
                    int first = __ffs(m) - 1;
                    contrib = (t <= first) ? (val & 0xffffffffull) : 0ull;
                } else {
                    contrib = val & 0xffffffffull;
                }
#pragma unroll
                for (int off = 16; off; off >>= 1)
                    contrib += __shfl_down_sync(0xffffffffu, contrib, off);
                contrib = __shfl_sync(0xffffffffu, contrib, 0);
                run += contrib;
                if (m) break;
                look -= 32;
            }
        }
        if (t == 0) {
            run_sh = run;
            if (bid > 0)
                atomicExch(&g_sstate[bid],
                           (2ull << 32) | (unsigned)(run + (ull)total));
        }
    }
    __syncthreads();
    if (i < N_NODES) {
        int off = (int)run_sh + incl - v;
        g_offs[i] = off;
        g_cursor[i] = off;
    }
}

// ---------------- CSR fill (direct fetch-and-add on cursor) ------------------
__global__ void k_fill(const int* __restrict__ src, const int* __restrict__ dst) {
    int i = blockIdx.x * blockDim.x + threadIdx.x;
    if (i >= N_EDGES) return;
    int pos = atomicAdd(&g_cursor[dst[i]], 1);
    g_adj[pos] = src[i];
}

// ---------------- gather aggregation: agg[n] = mean_{s in N(n)} x[s] --------
__global__ void k_gather(int phase) {
    const __half* __restrict__ x = phase ? g_h16 : g_x16;
    int w = (blockIdx.x * blockDim.x + threadIdx.x) >> 5;
    int lane = threadIdx.x & 31;
    if (w >= N_NODES) return;
    int beg = g_offs[w];
    int d   = g_degi[w];
    float4 acc0 = make_float4(0.f, 0.f, 0.f, 0.f);
    float4 acc1 = make_float4(0.f, 0.f, 0.f, 0.f);
    float4 acc2 = make_float4(0.f, 0.f, 0.f, 0.f);
    float4 acc3 = make_float4(0.f, 0.f, 0.f, 0.f);
    int i = 0;
    for (; i + 4 <= d; i += 4) {
        int s0 = g_adj[beg + i],     s1 = g_adj[beg + i + 1];
        int s2 = g_adj[beg + i + 2], s3 = g_adj[beg + i + 3];
        float4 v0 = ld_h4(x + (size_t)s0 * HID + lane * 4);
        float4 v1 = ld_h4(x + (size_t)s1 * HID + lane * 4);
        float4 v2 = ld_h4(x + (size_t)s2 * HID + lane * 4);
        float4 v3 = ld_h4(x + (size_t)s3 * HID + lane * 4);
        acc0.x += v0.x; acc0.y += v0.y; acc0.z += v0.z; acc0.w += v0.w;
        acc1.x += v1.x; acc1.y += v1.y; acc1.z += v1.z; acc1.w += v1.w;
        acc2.x += v2.x; acc2.y += v2.y; acc2.z += v2.z; acc2.w += v2.w;
        acc3.x += v3.x; acc3.y += v3.y; acc3.z += v3.z; acc3.w += v3.w;
    }
    for (; i < d; i++) {
        int s0 = g_adj[beg + i];
        float4 v0 = ld_h4(x + (size_t)s0 * HID + lane * 4);
        acc0.x += v0.x; acc0.y += v0.y; acc0.z += v0.z; acc0.w += v0.w;
    }
    float inv = 1.0f / (float)max(d, 1);
    float4 o;
    o.x = (acc0.x + acc1.x + acc2.x + acc3.x) * inv;
    o.y = (acc0.y + acc1.y + acc2.y + acc3.y) * inv;
    o.z = (acc0.z + acc1.z + acc2.z + acc3.z) * inv;
    o.w = (acc0.w + acc1.w + acc2.w + acc3.w) * inv;
    st_h4(g_agg16 + (size_t)w * HID + lane * 4, o);
}

// ---------------- fp16 mma.sync fused dual GEMM + bias + relu (+pool) -------
// out = relu( [agg | xin] @ [wl | wr]^T + bias ), K=256, 128x128 CTA tile
#define MM_SMEM (32768 + 512)

__global__ __launch_bounds__(256) void k_mm_mma(const __half* __restrict__ xin,
                                                const float* __restrict__ wl,
                                                const float* __restrict__ wr,
                                                const float* __restrict__ bias,
                                                __half* __restrict__ out16,
                                                const int* __restrict__ batch,
                                                int do_pool) {
    extern __shared__ uint32_t smu[];
    uint32_t* sA = smu;                 // 4096 u32
    uint32_t* sB = smu + 4096;          // 4096 u32
    float* sBias = (float*)(smu + 8192);
    int tid = threadIdx.x;
    int lane = tid & 31, wid = tid >> 5;
    int warp_m = wid & 1;           // 2 warps over M (64 rows each)
    int warp_n = wid >> 1;          // 4 warps over N (32 cols each)
    int row0 = blockIdx.x * 128;
    if (tid < 128) sBias[tid] = bias[tid];

    float c[4][4][4];
#pragma unroll
    for (int mt = 0; mt < 4; mt++)
#pragma unroll
        for (int nt = 0; nt < 4; nt++)
#pragma unroll
            for (int r = 0; r < 4; r++) c[mt][nt][r] = 0.f;

    for (int ch = 0; ch < 4; ch++) {
        const __half* srcA = ((ch < 2) ? g_agg16 : xin) + (ch & 1) * 64;
        const float* srcW = (ch < 2) ? wl : wr;
        int kw = (ch & 1) * 64;
        __syncthreads();
        // A tile: 128 rows x 64 k fp16 -> fragment-order smem (16B loads)
#pragma unroll
        for (int i = 0; i < 4; i++) {
            int idx = tid + i * 256;         // 0..1023
            int r = idx >> 3, q = idx & 7;   // row, 8-half group
            int rg = row0 + r;
            uint4 u = make_uint4(0u, 0u, 0u, 0u);
            if (rg < N_NODES)
                u = *(const uint4*)(srcA + (size_t)rg * 128 + q * 8);
            int mt = r >> 4, ri = r & 15;
            int k16 = q >> 1;
            int reg = (ri >= 8 ? 1 : 0) + 2 * (q & 1);
            uint32_t base = ((mt * 4 + k16) * 32) * 4 + reg;
            uint32_t lb = (ri & 7) * 16;     // lane*4 in u32 units
            sA[base + lb +  0] = u.x;
            sA[base + lb +  4] = u.y;
            sA[base + lb +  8] = u.z;
            sA[base + lb + 12] = u.w;
        }
        // B tile: w[n][k] fp32 -> fp16 fragment-order smem
#pragma unroll
        for (int i = 0; i < 8; i++) {
            int idx = tid + i * 256;         // 0..2047
            int n = idx >> 4, q = idx & 15;  // out-col, float4 group
            float4 v = *(const float4*)(srcW + (size_t)n * 128 + kw + q * 4);
            uint32_t h0, h1;
            *(__half2*)&h0 = __floats2half2_rn(v.x, v.y);
            *(__half2*)&h1 = __floats2half2_rn(v.z, v.w);
            int nt = n >> 3;
            int k16 = q >> 2;
            int reg = (q >> 1) & 1;
            int l0 = (n & 7) * 4 + 2 * (q & 1);
            uint32_t base = ((nt * 4 + k16) * 32) * 2 + reg;
            sB[base + l0 * 2]       = h0;
            sB[base + (l0 + 1) * 2] = h1;
        }
        __syncthreads();
#pragma unroll
        for (int k16 = 0; k16 < 4; k16++) {
            uint32_t a[4][4], b[4][2];
#pragma unroll
            for (int mt = 0; mt < 4; mt++)
                *(uint4*)a[mt] = *(const uint4*)
                    (sA + (((warp_m * 4 + mt) * 4 + k16) * 32 + lane) * 4);
#pragma unroll
            for (int nt = 0; nt < 4; nt++)
                *(uint2*)b[nt] = *(const uint2*)
                    (sB + (((warp_n * 4 + nt) * 4 + k16) * 32 + lane) * 2);
#pragma unroll
            for (int mt = 0; mt < 4; mt++)
#pragma unroll
                for (int nt = 0; nt < 4; nt++)
                    mma_f16(c[mt][nt], a[mt], b[nt]);
        }
    }

    // epilogue: bias + relu; layer1 -> fp16 store; layer2 -> pool red-add
    int g = lane >> 2, tg = lane & 3;
#pragma unroll
    for (int mt = 0; mt < 4; mt++) {
        int row = row0 + warp_m * 64 + mt * 16 + g;
        int g0 = (do_pool && row < N_NODES) ? batch[row] : 0;
        int g1 = (do_pool && row + 8 < N_NODES) ? batch[row + 8] : 0;
#pragma unroll
        for (int nt = 0; nt < 4; nt++) {
            int col = warp_n * 32 + nt * 8 + tg * 2;
            float b0 = sBias[col], b1 = sBias[col + 1];
            float r0x = fmaxf(c[mt][nt][0] + b0, 0.f);
            float r0y = fmaxf(c[mt][nt][1] + b1, 0.f);
            float r1x = fmaxf(c[mt][nt][2] + b0, 0.f);
            float r1y = fmaxf(c[mt][nt][3] + b1, 0.f);
            if (do_pool) {
                if (row < N_NODES)
                    red_add_v2(g_gsum + (size_t)g0 * 128 + col, r0x, r0y);
                if (row + 8 < N_NODES)
                    red_add_v2(g_gsum + (size_t)g1 * 128 + col, r1x, r1y);
            } else {
                if (row < N_NODES)
                    *(__half2*)(out16 + (size_t)row * 128 + col) = __floats2half2_rn(r0x, r0y);
                if (row + 8 < N_NODES)
                    *(__half2*)(out16 + (size_t)(row + 8) * 128 + col) = __floats2half2_rn(r1x, r1y);
            }
        }
    }
}

// ---------------- final linear head -----------------------------------------
__global__ void k_out(const float* __restrict__ wout, const float* __restrict__ bout,
                      float* __restrict__ y) {
    int g = blockIdx.x;
    __shared__ float row[128];
    float inv = 1.0f / fmaxf(g_gcnt[g], 1.0f);
    row[threadIdx.x] = g_gsum[g * 128 + threadIdx.x] * inv;
    __syncthreads();
    if (threadIdx.x < N_CLS) {
        float s = bout[threadIdx.x];
        const float* wrow = wout + threadIdx.x * 128;
#pragma unroll 16
        for (int d = 0; d < 128; d++) s += row[d] * wrow[d];
        y[g * N_CLS + threadIdx.x] = s;
    }
}

// ---------------- launch -----------------------------------------------------
extern "C" void kernel_launch(void* const* d_in, const int* in_sizes, int n_in,
                              void* d_out, int out_size) {
    const int*   x_tokens = (const int*)  d_in[0];
    const int*   ei       = (const int*)  d_in[1];
    const int*   batch    = (const int*)  d_in[2];
    const float* emb      = (const float*)d_in[3];
    const float* w1l      = (const float*)d_in[4];
    const float* b1       = (const float*)d_in[5];
    const float* w1r      = (const float*)d_in[6];
    const float* w2l      = (const float*)d_in[7];
    const float* b2       = (const float*)d_in[8];
    const float* w2r      = (const float*)d_in[9];
    const float* wout     = (const float*)d_in[10];
    const float* bout     = (const float*)d_in[11];
    float* y = (float*)d_out;

    const int* src = ei;
    const int* dst = ei + N_EDGES;

    cudaFuncSetAttribute(k_mm_mma, cudaFuncAttributeMaxDynamicSharedMemorySize,
                         MM_SMEM);

    __half* p_x16;  cudaGetSymbolAddress((void**)&p_x16, g_x16);
    __half* p_h16;  cudaGetSymbolAddress((void**)&p_h16, g_h16);

    k_zero_pre<<<1024, 256>>>(emb);

    // fork: embed on g_s1, CSR build on main stream
    cudaEventRecord(g_evFork, 0);
    cudaStreamWaitEvent(g_s1, g_evFork, 0);
    k_embed  <<<(N_NODES * 32 + 255) / 256, 256, 0, g_s1>>>(x_tokens);
    k_counts <<<COUNT_BLOCKS, 256>>>(dst, batch);
    k_scan   <<<NBLK, 256>>>();
    k_fill   <<<COUNT_BLOCKS, 256>>>(src, dst);
    cudaEventRecord(g_evJoin, g_s1);
    cudaStreamWaitEvent(0, g_evJoin, 0);

    int mm_grid = (N_NODES + 127) / 128;   // 391
    k_gather <<<(N_NODES * 32 + 255) / 256, 256>>>(0);
    k_mm_mma <<<mm_grid, 256, MM_SMEM>>>(p_x16, w1l, w1r, b1, p_h16, batch, 0);

    k_gather <<<(N_NODES * 32 + 255) / 256, 256>>>(1);
    k_mm_mma <<<mm_grid, 256, MM_SMEM>>>(p_h16, w2l, w2r, b2, nullptr, batch, 1);

    k_out    <<<N_GRAPHS, 128>>>(wout, bout, y);
}

// round 12
// speedup vs baseline: 1.0013x; 1.0013x over previous
#include <cuda_runtime.h>
#include <cuda_fp16.h>
#include <cstdint>

#define N_NODES  50000
#define N_EDGES  600000
#define BAG      16
#define VOCAB    10000
#define EMB      128
#define HID      128
#define N_GRAPHS 512
#define N_CLS    10
#define PAD_IDX  1
#define NBLK 196   // ceil(N_NODES/256)

#define EMBED_BLOCKS ((N_NODES * 32 + 255) / 256)     // 6250
#define COUNT_BLOCKS ((N_EDGES + 255) / 256)          // 2344

typedef unsigned long long ull;

// ---------------- scratch (static device globals; no allocation) ------------
__device__ __align__(16) __half g_x16 [N_NODES * HID];  // embed out / features
__device__ __align__(16) __half g_h16 [N_NODES * HID];  // layer1 out
__device__ __align__(16) __half g_agg16[N_NODES * HID]; // neighbor mean
__device__ __align__(16) __half g_tab16[VOCAB * EMB];   // fp16 emb table
__device__ __align__(16) float g_gsum[N_GRAPHS * HID];
__device__ __align__(16) float g_gcnt[N_GRAPHS];
// CSR
__device__ int g_degi  [N_NODES];
__device__ int g_offs  [N_NODES];
__device__ int g_cursor[N_NODES];
__device__ int g_adj   [N_EDGES];
__device__ ull g_sstate[NBLK];     // decoupled-lookback state

// ---------------- helpers ----------------------------------------------------
__device__ __forceinline__ void red_add_v2(float* p, float a, float b) {
    asm volatile("red.global.add.v2.f32 [%0], {%1,%2};"
                 :: "l"(p), "f"(a), "f"(b) : "memory");
}
__device__ __forceinline__ void mma_f16(float* c, const uint32_t* a, const uint32_t* b) {
    asm volatile("mma.sync.aligned.m16n8k16.row.col.f32.f16.f16.f32 "
        "{%0,%1,%2,%3}, {%4,%5,%6,%7}, {%8,%9}, {%0,%1,%2,%3};"
        : "+f"(c[0]), "+f"(c[1]), "+f"(c[2]), "+f"(c[3])
        : "r"(a[0]), "r"(a[1]), "r"(a[2]), "r"(a[3]), "r"(b[0]), "r"(b[1]));
}
__device__ __forceinline__ float4 ld_h4(const __half* p) {
    uint2 u = *(const uint2*)p;
    __half2 h0 = *(__half2*)&u.x, h1 = *(__half2*)&u.y;
    float2 f0 = __half22float2(h0), f1 = __half22float2(h1);
    return make_float4(f0.x, f0.y, f1.x, f1.y);
}
__device__ __forceinline__ void st_h4(__half* p, float4 v) {
    uint2 u;
    *(__half2*)&u.x = __floats2half2_rn(v.x, v.y);
    *(__half2*)&u.y = __floats2half2_rn(v.z, v.w);
    *(uint2*)p = u;
}

// ---------------- zeroing + table prep --------------------------------------
__global__ void k_zero_pre(const float* __restrict__ table) {
    int t = blockIdx.x * blockDim.x + threadIdx.x;
    int stride = gridDim.x * blockDim.x;
    for (int i = t; i < N_NODES; i += stride) g_degi[i] = 0;
    for (int i = t; i < N_GRAPHS; i += stride) g_gcnt[i] = 0.f;
    for (int i = t; i < N_GRAPHS * HID; i += stride) g_gsum[i] = 0.f;
    for (int i = t; i < NBLK; i += stride) g_sstate[i] = 0ull;
    for (int i = t; i < VOCAB * EMB / 4; i += stride) {
        float4 v = ((const float4*)table)[i];
        st_h4(g_tab16 + i * 4, v);
    }
}

// ---------------- embedding bag (mean) + degree/graph counts (merged) -------
__global__ void k_embed_counts(const int* __restrict__ tokens,
                               const int* __restrict__ dst,
                               const int* __restrict__ batch) {
    if (blockIdx.x >= EMBED_BLOCKS) {
        int i = (blockIdx.x - EMBED_BLOCKS) * blockDim.x + threadIdx.x;
        if (i < N_EDGES) atomicAdd(&g_degi[dst[i]], 1);
        if (i < N_NODES) atomicAdd(&g_gcnt[batch[i]], 1.0f);
        return;
    }
    int w = (blockIdx.x * blockDim.x + threadIdx.x) >> 5;
    int lane = threadIdx.x & 31;
    if (w >= N_NODES) return;
    const int* tk = tokens + w * BAG;
    float4 acc = make_float4(0.f, 0.f, 0.f, 0.f);
    int cnt = 0;
#pragma unroll
    for (int t = 0; t < BAG; t++) {
        int tok = tk[t];
        if (tok != PAD_IDX) {
            cnt++;
            float4 e = ld_h4(g_tab16 + (size_t)tok * EMB + lane * 4);
            acc.x += e.x; acc.y += e.y; acc.z += e.z; acc.w += e.w;
        }
    }
    float inv = 1.0f / (float)max(cnt, 1);
    acc.x *= inv; acc.y *= inv; acc.z *= inv; acc.w *= inv;
    st_h4(g_x16 + (size_t)w * HID + lane * 4, acc);
}

// ---------------- single-kernel exclusive scan (decoupled lookback) ----------
// shuffle-based block scan; also seeds g_cursor[i] = offs[i] for fill
__global__ void k_scan() {
    __shared__ int wsum[8];
    __shared__ ull run_sh;
    int t = threadIdx.x, bid = blockIdx.x;
    int lane = t & 31, wrp = t >> 5;
    int i = bid * 256 + t;
    int v = (i < N_NODES) ? g_degi[i] : 0;
    // warp inclusive scan
    int sc = v;
#pragma unroll
    for (int o = 1; o < 32; o <<= 1) {
        int x = __shfl_up_sync(0xffffffffu, sc, o);
        if (lane >= o) sc += x;
    }
    if (lane == 31) wsum[wrp] = sc;
    __syncthreads();
    int wbase = 0, total;
    {
        int ws = (lane < 8) ? wsum[lane] : 0;
#pragma unroll
        for (int o = 1; o < 8; o <<= 1) {
            int x = __shfl_up_sync(0xffffffffu, ws, o);
            if (lane >= o) ws += x;
        }
        total  = __shfl_sync(0xffffffffu, ws, 7);
        int wb = __shfl_sync(0xffffffffu, ws, wrp) ;   // inclusive up to wrp
        wbase  = wb - wsum[wrp];                        // exclusive warp base
    }
    int incl = wbase + sc;
    if (t == 0) {
        ull st = ((ull)(bid == 0 ? 2 : 1) << 32) | (unsigned)total;
        atomicExch(&g_sstate[bid], st);
    }
    if (t < 32) {
        ull run = 0;
        if (bid > 0) {
            int look = bid - 1;
            while (true) {
                int j = look - t;
                ull val; int stt;
                if (j >= 0) {
                    do { val = atomicAdd(&g_sstate[j], 0ull); stt = (int)(val >> 32); }
                    while (stt == 0);
                } else { val = (2ull << 32); stt = 2; }
                unsigned m = __ballot_sync(0xffffffffu, stt == 2);
                ull contrib;
                if (m) {
                    int first = __ffs(m) - 1;
                    contrib = (t <= first) ? (val & 0xffffffffull) : 0ull;
                } else {
                    contrib = val & 0xffffffffull;
                }
#pragma unroll
                for (int off = 16; off; off >>= 1)
                    contrib += __shfl_down_sync(0xffffffffu, contrib, off);
                contrib = __shfl_sync(0xffffffffu, contrib, 0);
                run += contrib;
                if (m) break;
                look -= 32;
            }
        }
        if (t == 0) {
            run_sh = run;
            if (bid > 0)
                atomicExch(&g_sstate[bid],
                           (2ull << 32) | (unsigned)(run + (ull)total));
        }
    }
    __syncthreads();
    if (i < N_NODES) {
        int off = (int)run_sh + incl - v;
        g_offs[i] = off;
        g_cursor[i] = off;
    }
}

// ---------------- CSR fill (direct fetch-and-add on cursor) ------------------
__global__ void k_fill(const int* __restrict__ src, const int* __restrict__ dst) {
    int i = blockIdx.x * blockDim.x + threadIdx.x;
    if (i >= N_EDGES) return;
    int pos = atomicAdd(&g_cursor[dst[i]], 1);
    g_adj[pos] = src[i];
}

// ---------------- gather aggregation: agg[n] = mean_{s in N(n)} x[s] --------
__global__ void k_gather(int phase) {
    const __half* __restrict__ x = phase ? g_h16 : g_x16;
    int w = (blockIdx.x * blockDim.x + threadIdx.x) >> 5;
    int lane = threadIdx.x & 31;
    if (w >= N_NODES) return;
    int beg = g_offs[w];
    int d   = g_degi[w];
    float4 acc0 = make_float4(0.f, 0.f, 0.f, 0.f);
    float4 acc1 = make_float4(0.f, 0.f, 0.f, 0.f);
    float4 acc2 = make_float4(0.f, 0.f, 0.f, 0.f);
    float4 acc3 = make_float4(0.f, 0.f, 0.f, 0.f);
    int i = 0;
    for (; i + 4 <= d; i += 4) {
        int s0 = g_adj[beg + i],     s1 = g_adj[beg + i + 1];
        int s2 = g_adj[beg + i + 2], s3 = g_adj[beg + i + 3];
        float4 v0 = ld_h4(x + (size_t)s0 * HID + lane * 4);
        float4 v1 = ld_h4(x + (size_t)s1 * HID + lane * 4);
        float4 v2 = ld_h4(x + (size_t)s2 * HID + lane * 4);
        float4 v3 = ld_h4(x + (size_t)s3 * HID + lane * 4);
        acc0.x += v0.x; acc0.y += v0.y; acc0.z += v0.z; acc0.w += v0.w;
        acc1.x += v1.x; acc1.y += v1.y; acc1.z += v1.z; acc1.w += v1.w;
        acc2.x += v2.x; acc2.y += v2.y; acc2.z += v2.z; acc2.w += v2.w;
        acc3.x += v3.x; acc3.y += v3.y; acc3.z += v3.z; acc3.w += v3.w;
    }
    for (; i < d; i++) {
        int s0 = g_adj[beg + i];
        float4 v0 = ld_h4(x + (size_t)s0 * HID + lane * 4);
        acc0.x += v0.x; acc0.y += v0.y; acc0.z += v0.z; acc0.w += v0.w;
    }
    float inv = 1.0f / (float)max(d, 1);
    float4 o;
    o.x = (acc0.x + acc1.x + acc2.x + acc3.x) * inv;
    o.y = (acc0.y + acc1.y + acc2.y + acc3.y) * inv;
    o.z = (acc0.z + acc1.z + acc2.z + acc3.z) * inv;
    o.w = (acc0.w + acc1.w + acc2.w + acc3.w) * inv;
    st_h4(g_agg16 + (size_t)w * HID + lane * 4, o);
}

// ---------------- fp16 mma.sync fused dual GEMM + bias + relu (+pool) -------
// out = relu( [agg | xin] @ [wl | wr]^T + bias ), K=256, 128x128 CTA tile
#define MM_SMEM (32768 + 512)

__global__ __launch_bounds__(256) void k_mm_mma(const __half* __restrict__ xin,
                                                const float* __restrict__ wl,
                                                const float* __restrict__ wr,
                                                const float* __restrict__ bias,
                                                __half* __restrict__ out16,
                                                const int* __restrict__ batch,
                                                int do_pool) {
    extern __shared__ uint32_t smu[];
    uint32_t* sA = smu;                 // 4096 u32
    uint32_t* sB = smu + 4096;          // 4096 u32
    float* sBias = (float*)(smu + 8192);
    int tid = threadIdx.x;
    int lane = tid & 31, wid = tid >> 5;
    int warp_m = wid & 1;           // 2 warps over M (64 rows each)
    int warp_n = wid >> 1;          // 4 warps over N (32 cols each)
    int row0 = blockIdx.x * 128;
    if (tid < 128) sBias[tid] = bias[tid];

    float c[4][4][4];
#pragma unroll
    for (int mt = 0; mt < 4; mt++)
#pragma unroll
        for (int nt = 0; nt < 4; nt++)
#pragma unroll
            for (int r = 0; r < 4; r++) c[mt][nt][r] = 0.f;

    for (int ch = 0; ch < 4; ch++) {
        const __half* srcA = ((ch < 2) ? g_agg16 : xin) + (ch & 1) * 64;
        const float* srcW = (ch < 2) ? wl : wr;
        int kw = (ch & 1) * 64;
        __syncthreads();
        // A tile: 128 rows x 64 k fp16 -> fragment-order smem (16B loads)
#pragma unroll
        for (int i = 0; i < 4; i++) {
            int idx = tid + i * 256;         // 0..1023
            int r = idx >> 3, q = idx & 7;   // row, 8-half group
            int rg = row0 + r;
            uint4 u = make_uint4(0u, 0u, 0u, 0u);
            if (rg < N_NODES)
                u = *(const uint4*)(srcA + (size_t)rg * 128 + q * 8);
            int mt = r >> 4, ri = r & 15;
            int k16 = q >> 1;
            int reg = (ri >= 8 ? 1 : 0) + 2 * (q & 1);
            uint32_t base = ((mt * 4 + k16) * 32) * 4 + reg;
            uint32_t lb = (ri & 7) * 16;     // lane*4 in u32 units
            sA[base + lb +  0] = u.x;
            sA[base + lb +  4] = u.y;
            sA[base + lb +  8] = u.z;
            sA[base + lb + 12] = u.w;
        }
        // B tile: w[n][k] fp32 -> fp16 fragment-order smem
#pragma unroll
        for (int i = 0; i < 8; i++) {
            int idx = tid + i * 256;         // 0..2047
            int n = idx >> 4, q = idx & 15;  // out-col, float4 group
            float4 v = *(const float4*)(srcW + (size_t)n * 128 + kw + q * 4);
            uint32_t h0, h1;
            *(__half2*)&h0 = __floats2half2_rn(v.x, v.y);
            *(__half2*)&h1 = __floats2half2_rn(v.z, v.w);
            int nt = n >> 3;
            int k16 = q >> 2;
            int reg = (q >> 1) & 1;
            int l0 = (n & 7) * 4 + 2 * (q & 1);
            uint32_t base = ((nt * 4 + k16) * 32) * 2 + reg;
            sB[base + l0 * 2]       = h0;
            sB[base + (l0 + 1) * 2] = h1;
        }
        __syncthreads();
#pragma unroll
        for (int k16 = 0; k16 < 4; k16++) {
            uint32_t a[4][4], b[4][2];
#pragma unroll
            for (int mt = 0; mt < 4; mt++)
                *(uint4*)a[mt] = *(const uint4*)
                    (sA + (((warp_m * 4 + mt) * 4 + k16) * 32 + lane) * 4);
#pragma unroll
            for (int nt = 0; nt < 4; nt++)
                *(uint2*)b[nt] = *(const uint2*)
                    (sB + (((warp_n * 4 + nt) * 4 + k16) * 32 + lane) * 2);
#pragma unroll
            for (int mt = 0; mt < 4; mt++)
#pragma unroll
                for (int nt = 0; nt < 4; nt++)
                    mma_f16(c[mt][nt], a[mt], b[nt]);
        }
    }

    // epilogue: bias + relu; layer1 -> fp16 store; layer2 -> pool red-add
    int g = lane >> 2, tg = lane & 3;
#pragma unroll
    for (int mt = 0; mt < 4; mt++) {
        int row = row0 + warp_m * 64 + mt * 16 + g;
        int g0 = (do_pool && row < N_NODES) ? batch[row] : 0;
        int g1 = (do_pool && row + 8 < N_NODES) ? batch[row + 8] : 0;
#pragma unroll
        for (int nt = 0; nt < 4; nt++) {
            int col = warp_n * 32 + nt * 8 + tg * 2;
            float b0 = sBias[col], b1 = sBias[col + 1];
            float r0x = fmaxf(c[mt][nt][0] + b0, 0.f);
            float r0y = fmaxf(c[mt][nt][1] + b1, 0.f);
            float r1x = fmaxf(c[mt][nt][2] + b0, 0.f);
            float r1y = fmaxf(c[mt][nt][3] + b1, 0.f);
            if (do_pool) {
                if (row < N_NODES)
                    red_add_v2(g_gsum + (size_t)g0 * 128 + col, r0x, r0y);
                if (row + 8 < N_NODES)
                    red_add_v2(g_gsum + (size_t)g1 * 128 + col, r1x, r1y);
            } else {
                if (row < N_NODES)
                    *(__half2*)(out16 + (size_t)row * 128 + col) = __floats2half2_rn(r0x, r0y);
                if (row + 8 < N_NODES)
                    *(__half2*)(out16 + (size_t)(row + 8) * 128 + col) = __floats2half2_rn(r1x, r1y);
            }
        }
    }
}

// ---------------- final linear head -----------------------------------------
__global__ void k_out(const float* __restrict__ wout, const float* __restrict__ bout,
                      float* __restrict__ y) {
    int g = blockIdx.x;
    __shared__ float row[128];
    float inv = 1.0f / fmaxf(g_gcnt[g], 1.0f);
    row[threadIdx.x] = g_gsum[g * 128 + threadIdx.x] * inv;
    __syncthreads();
    if (threadIdx.x < N_CLS) {
        float s = bout[threadIdx.x];
        const float* wrow = wout + threadIdx.x * 128;
#pragma unroll 16
        for (int d = 0; d < 128; d++) s += row[d] * wrow[d];
        y[g * N_CLS + threadIdx.x] = s;
    }
}

// ---------------- launch -----------------------------------------------------
extern "C" void kernel_launch(void* const* d_in, const int* in_sizes, int n_in,
                              void* d_out, int out_size) {
    const int*   x_tokens = (const int*)  d_in[0];
    const int*   ei       = (const int*)  d_in[1];
    const int*   batch    = (const int*)  d_in[2];
    const float* emb      = (const float*)d_in[3];
    const float* w1l      = (const float*)d_in[4];
    const float* b1       = (const float*)d_in[5];
    const float* w1r      = (const float*)d_in[6];
    const float* w2l      = (const float*)d_in[7];
    const float* b2       = (const float*)d_in[8];
    const float* w2r      = (const float*)d_in[9];
    const float* wout     = (const float*)d_in[10];
    const float* bout     = (const float*)d_in[11];
    float* y = (float*)d_out;

    const int* src = ei;
    const int* dst = ei + N_EDGES;

    cudaFuncSetAttribute(k_mm_mma, cudaFuncAttributeMaxDynamicSharedMemorySize,
                         MM_SMEM);

    __half* p_x16;  cudaGetSymbolAddress((void**)&p_x16, g_x16);
    __half* p_h16;  cudaGetSymbolAddress((void**)&p_h16, g_h16);

    k_zero_pre<<<1024, 256>>>(emb);
    k_embed_counts<<<EMBED_BLOCKS + COUNT_BLOCKS, 256>>>(x_tokens, dst, batch);
    k_scan   <<<NBLK, 256>>>();
    k_fill   <<<COUNT_BLOCKS, 256>>>(src, dst);

    int mm_grid = (N_NODES + 127) / 128;   // 391
    k_gather <<<(N_NODES * 32 + 255) / 256, 256>>>(0);
    k_mm_mma <<<mm_grid, 256, MM_SMEM>>>(p_x16, w1l, w1r, b1, p_h16, batch, 0);

    k_gather <<<(N_NODES * 32 + 255) / 256, 256>>>(1);
    k_mm_mma <<<mm_grid, 256, MM_SMEM>>>(p_h16, w2l, w2r, b2, nullptr, batch, 1);

    k_out    <<<N_GRAPHS, 128>>>(wout, bout, y);
}

// round 13
// speedup vs baseline: 1.0497x; 1.0484x over previous
#include <cuda_runtime.h>
#include <cuda_fp16.h>
#include <cstdint>

#define N_NODES  50000
#define N_EDGES  600000
#define BAG      16
#define VOCAB    10000
#define EMB      128
#define HID      128
#define N_GRAPHS 512
#define N_CLS    10
#define PAD_IDX  1
#define NBLK 196   // ceil(N_NODES/256)

#define EMBED_BLOCKS ((N_NODES * 32 + 255) / 256)       // 6250
#define EDGE4_BLOCKS ((N_EDGES / 4 + 255) / 256)        // 586
#define NODE4_BLOCKS ((N_NODES / 4 + 255) / 256)        // 49
#define FILL4_BLOCKS ((N_EDGES / 4 + 255) / 256)        // 586

typedef unsigned long long ull;

// ---------------- scratch (static device globals; no allocation) ------------
__device__ __align__(16) __half g_x16 [N_NODES * HID];  // embed out / features
__device__ __align__(16) __half g_h16 [N_NODES * HID];  // layer1 out
__device__ __align__(16) __half g_agg16[N_NODES * HID]; // neighbor mean
__device__ __align__(16) __half g_tab16[VOCAB * EMB];   // fp16 emb table
__device__ __align__(16) float g_gsum[N_GRAPHS * HID];
__device__ __align__(16) float g_gcnt[N_GRAPHS];
// CSR
__device__ int g_degi  [N_NODES];
__device__ int g_offs  [N_NODES];
__device__ int g_cursor[N_NODES];
__device__ int g_adj   [N_EDGES];
__device__ ull g_sstate[NBLK];     // decoupled-lookback state

// ---------------- helpers ----------------------------------------------------
__device__ __forceinline__ void red_add_v2(float* p, float a, float b) {
    asm volatile("red.global.add.v2.f32 [%0], {%1,%2};"
                 :: "l"(p), "f"(a), "f"(b) : "memory");
}
__device__ __forceinline__ void mma_f16(float* c, const uint32_t* a, const uint32_t* b) {
    asm volatile("mma.sync.aligned.m16n8k16.row.col.f32.f16.f16.f32 "
        "{%0,%1,%2,%3}, {%4,%5,%6,%7}, {%8,%9}, {%0,%1,%2,%3};"
        : "+f"(c[0]), "+f"(c[1]), "+f"(c[2]), "+f"(c[3])
        : "r"(a[0]), "r"(a[1]), "r"(a[2]), "r"(a[3]), "r"(b[0]), "r"(b[1]));
}
__device__ __forceinline__ float4 ld_h4(const __half* p) {
    uint2 u = *(const uint2*)p;
    __half2 h0 = *(__half2*)&u.x, h1 = *(__half2*)&u.y;
    float2 f0 = __half22float2(h0), f1 = __half22float2(h1);
    return make_float4(f0.x, f0.y, f1.x, f1.y);
}
__device__ __forceinline__ void st_h4(__half* p, float4 v) {
    uint2 u;
    *(__half2*)&u.x = __floats2half2_rn(v.x, v.y);
    *(__half2*)&u.y = __floats2half2_rn(v.z, v.w);
    *(uint2*)p = u;
}

// ---------------- zeroing + table prep --------------------------------------
__global__ void k_zero_pre(const float* __restrict__ table) {
    int t = blockIdx.x * blockDim.x + threadIdx.x;
    int stride = gridDim.x * blockDim.x;
    for (int i = t; i < N_NODES; i += stride) g_degi[i] = 0;
    for (int i = t; i < N_GRAPHS; i += stride) g_gcnt[i] = 0.f;
    for (int i = t; i < N_GRAPHS * HID; i += stride) g_gsum[i] = 0.f;
    for (int i = t; i < NBLK; i += stride) g_sstate[i] = 0ull;
    for (int i = t; i < VOCAB * EMB / 4; i += stride) {
        float4 v = ((const float4*)table)[i];
        st_h4(g_tab16 + i * 4, v);
    }
}

// ---------------- embedding bag (mean) + degree/graph counts (merged) -------
__global__ void k_embed_counts(const int* __restrict__ tokens,
                               const int* __restrict__ dst,
                               const int* __restrict__ batch) {
    if (blockIdx.x >= EMBED_BLOCKS) {
        int b = blockIdx.x - EMBED_BLOCKS;
        if (b < EDGE4_BLOCKS) {
            int i = (b * 256 + threadIdx.x) * 4;
            if (i + 4 <= N_EDGES) {          // N_EDGES % 4 == 0
                int4 d4 = *(const int4*)(dst + i);
                atomicAdd(&g_degi[d4.x], 1);
                atomicAdd(&g_degi[d4.y], 1);
                atomicAdd(&g_degi[d4.z], 1);
                atomicAdd(&g_degi[d4.w], 1);
            }
        } else {
            int i = ((b - EDGE4_BLOCKS) * 256 + threadIdx.x) * 4;
            if (i + 4 <= N_NODES) {          // N_NODES % 4 == 0
                int4 b4 = *(const int4*)(batch + i);
                atomicAdd(&g_gcnt[b4.x], 1.0f);
                atomicAdd(&g_gcnt[b4.y], 1.0f);
                atomicAdd(&g_gcnt[b4.z], 1.0f);
                atomicAdd(&g_gcnt[b4.w], 1.0f);
            }
        }
        return;
    }
    int w = (blockIdx.x * blockDim.x + threadIdx.x) >> 5;
    int lane = threadIdx.x & 31;
    if (w >= N_NODES) return;
    const int* tk = tokens + w * BAG;
    float4 acc = make_float4(0.f, 0.f, 0.f, 0.f);
    int cnt = 0;
#pragma unroll
    for (int t = 0; t < BAG; t++) {
        int tok = tk[t];
        if (tok != PAD_IDX) {
            cnt++;
            float4 e = ld_h4(g_tab16 + (size_t)tok * EMB + lane * 4);
            acc.x += e.x; acc.y += e.y; acc.z += e.z; acc.w += e.w;
        }
    }
    float inv = 1.0f / (float)max(cnt, 1);
    acc.x *= inv; acc.y *= inv; acc.z *= inv; acc.w *= inv;
    st_h4(g_x16 + (size_t)w * HID + lane * 4, acc);
}

// ---------------- single-kernel exclusive scan (decoupled lookback) ----------
// shuffle-based block scan; seeds g_cursor[i] = offs[i] for the fill
__global__ void k_scan() {
    __shared__ int wsum[8];
    __shared__ ull run_sh;
    int t = threadIdx.x, bid = blockIdx.x;
    int lane = t & 31, wrp = t >> 5;
    int i = bid * 256 + t;
    int v = (i < N_NODES) ? g_degi[i] : 0;
    int sc = v;
#pragma unroll
    for (int o = 1; o < 32; o <<= 1) {
        int x = __shfl_up_sync(0xffffffffu, sc, o);
        if (lane >= o) sc += x;
    }
    if (lane == 31) wsum[wrp] = sc;
    __syncthreads();
    int wbase = 0, total;
    {
        int ws = (lane < 8) ? wsum[lane] : 0;
#pragma unroll
        for (int o = 1; o < 8; o <<= 1) {
            int x = __shfl_up_sync(0xffffffffu, ws, o);
            if (lane >= o) ws += x;
        }
        total  = __shfl_sync(0xffffffffu, ws, 7);
        int wb = __shfl_sync(0xffffffffu, ws, wrp);
        wbase  = wb - wsum[wrp];
    }
    int incl = wbase + sc;
    if (t == 0) {
        ull st = ((ull)(bid == 0 ? 2 : 1) << 32) | (unsigned)total;
        atomicExch(&g_sstate[bid], st);
    }
    if (t < 32) {
        ull run = 0;
        if (bid > 0) {
            int look = bid - 1;
            while (true) {
                int j = look - t;
                ull val; int stt;
                if (j >= 0) {
                    do { val = atomicAdd(&g_sstate[j], 0ull); stt = (int)(val >> 32); }
                    while (stt == 0);
                } else { val = (2ull << 32); stt = 2; }
                unsigned m = __ballot_sync(0xffffffffu, stt == 2);
                ull contrib;
                if (m) {
                    int first = __ffs(m) - 1;
                    contrib = (t <= first) ? (val & 0xffffffffull) : 0ull;
                } else {
                    contrib = val & 0xffffffffull;
                }
#pragma unroll
                for (int off = 16; off; off >>= 1)
                    contrib += __shfl_down_sync(0xffffffffu, contrib, off);
                contrib = __shfl_sync(0xffffffffu, contrib, 0);
                run += contrib;
                if (m) break;
                look -= 32;
            }
        }
        if (t == 0) {
            run_sh = run;
            if (bid > 0)
                atomicExch(&g_sstate[bid],
                           (2ull << 32) | (unsigned)(run + (ull)total));
        }
    }
    __syncthreads();
    if (i < N_NODES) {
        int off = (int)run_sh + incl - v;
        g_offs[i] = off;
        g_cursor[i] = off;
    }
}

// ---------------- CSR fill (4 edges/thread, direct fetch-and-add) ------------
__global__ void k_fill(const int* __restrict__ src, const int* __restrict__ dst) {
    int i = (blockIdx.x * blockDim.x + threadIdx.x) * 4;
    if (i + 4 > N_EDGES) return;             // N_EDGES % 4 == 0
    int4 s4 = *(const int4*)(src + i);
    int4 d4 = *(const int4*)(dst + i);
    int p0 = atomicAdd(&g_cursor[d4.x], 1);
    int p1 = atomicAdd(&g_cursor[d4.y], 1);
    int p2 = atomicAdd(&g_cursor[d4.z], 1);
    int p3 = atomicAdd(&g_cursor[d4.w], 1);
    g_adj[p0] = s4.x;
    g_adj[p1] = s4.y;
    g_adj[p2] = s4.z;
    g_adj[p3] = s4.w;
}

// ---------------- gather aggregation: agg[n] = mean_{s in N(n)} x[s] --------
__global__ void k_gather(int phase) {
    const __half* __restrict__ x = phase ? g_h16 : g_x16;
    int w = (blockIdx.x * blockDim.x + threadIdx.x) >> 5;
    int lane = threadIdx.x & 31;
    if (w >= N_NODES) return;
    int beg = g_offs[w];
    int d   = g_degi[w];
    float4 acc0 = make_float4(0.f, 0.f, 0.f, 0.f);
    float4 acc1 = make_float4(0.f, 0.f, 0.f, 0.f);
    int i = 0;
    for (; i + 2 <= d; i += 2) {
        int s0 = g_adj[beg + i], s1 = g_adj[beg + i + 1];
        float4 v0 = ld_h4(x + (size_t)s0 * HID + lane * 4);
        float4 v1 = ld_h4(x + (size_t)s1 * HID + lane * 4);
        acc0.x += v0.x; acc0.y += v0.y; acc0.z += v0.z; acc0.w += v0.w;
        acc1.x += v1.x; acc1.y += v1.y; acc1.z += v1.z; acc1.w += v1.w;
    }
    if (i < d) {
        int s0 = g_adj[beg + i];
        float4 v0 = ld_h4(x + (size_t)s0 * HID + lane * 4);
        acc0.x += v0.x; acc0.y += v0.y; acc0.z += v0.z; acc0.w += v0.w;
    }
    float inv = 1.0f / (float)max(d, 1);
    float4 o;
    o.x = (acc0.x + acc1.x) * inv;
    o.y = (acc0.y + acc1.y) * inv;
    o.z = (acc0.z + acc1.z) * inv;
    o.w = (acc0.w + acc1.w) * inv;
    st_h4(g_agg16 + (size_t)w * HID + lane * 4, o);
}

// ---------------- fp16 mma.sync fused dual GEMM + bias + relu (+pool) -------
// out = relu( [agg | xin] @ [wl | wr]^T + bias ), K=256, 128x128 CTA tile
#define MM_SMEM (32768 + 512)

__global__ __launch_bounds__(256) void k_mm_mma(const __half* __restrict__ xin,
                                                const float* __restrict__ wl,
                                                const float* __restrict__ wr,
                                                const float* __restrict__ bias,
                                                __half* __restrict__ out16,
                                                const int* __restrict__ batch,
                                                int do_pool) {
    extern __shared__ uint32_t smu[];
    uint32_t* sA = smu;                 // 4096 u32
    uint32_t* sB = smu + 4096;          // 4096 u32
    float* sBias = (float*)(smu + 8192);
    int tid = threadIdx.x;
    int lane = tid & 31, wid = tid >> 5;
    int warp_m = wid & 1;           // 2 warps over M (64 rows each)
    int warp_n = wid >> 1;          // 4 warps over N (32 cols each)
    int row0 = blockIdx.x * 128;
    if (tid < 128) sBias[tid] = bias[tid];

    float c[4][4][4];
#pragma unroll
    for (int mt = 0; mt < 4; mt++)
#pragma unroll
        for (int nt = 0; nt < 4; nt++)
#pragma unroll
            for (int r = 0; r < 4; r++) c[mt][nt][r] = 0.f;

    for (int ch = 0; ch < 4; ch++) {
        const __half* srcA = ((ch < 2) ? g_agg16 : xin) + (ch & 1) * 64;
        const float* srcW = (ch < 2) ? wl : wr;
        int kw = (ch & 1) * 64;
        __syncthreads();
        // A tile: 128 rows x 64 k fp16 -> fragment-order smem (16B loads)
#pragma unroll
        for (int i = 0; i < 4; i++) {
            int idx = tid + i * 256;         // 0..1023
            int r = idx >> 3, q = idx & 7;   // row, 8-half group
            int rg = row0 + r;
            uint4 u = make_uint4(0u, 0u, 0u, 0u);
            if (rg < N_NODES)
                u = *(const uint4*)(srcA + (size_t)rg * 128 + q * 8);
            int mt = r >> 4, ri = r & 15;
            int k16 = q >> 1;
            int reg = (ri >= 8 ? 1 : 0) + 2 * (q & 1);
            uint32_t base = ((mt * 4 + k16) * 32) * 4 + reg;
            uint32_t lb = (ri & 7) * 16;     // lane*4 in u32 units
            sA[base + lb +  0] = u.x;
            sA[base + lb +  4] = u.y;
            sA[base + lb +  8] = u.z;
            sA[base + lb + 12] = u.w;
        }
        // B tile: w[n][k] fp32 -> fp16 fragment-order smem
#pragma unroll
        for (int i = 0; i < 8; i++) {
            int idx = tid + i * 256;         // 0..2047
            int n = idx >> 4, q = idx & 15;  // out-col, float4 group
            float4 v = *(const float4*)(srcW + (size_t)n * 128 + kw + q * 4);
            uint32_t h0, h1;
            *(__half2*)&h0 = __floats2half2_rn(v.x, v.y);
            *(__half2*)&h1 = __floats2half2_rn(v.z, v.w);
            int nt = n >> 3;
            int k16 = q >> 2;
            int reg = (q >> 1) & 1;
            int l0 = (n & 7) * 4 + 2 * (q & 1);
            uint32_t base = ((nt * 4 + k16) * 32) * 2 + reg;
            sB[base + l0 * 2]       = h0;
            sB[base + (l0 + 1) * 2] = h1;
        }
        __syncthreads();
#pragma unroll
        for (int k16 = 0; k16 < 4; k16++) {
            uint32_t a[4][4], b[4][2];
#pragma unroll
            for (int mt = 0; mt < 4; mt++)
                *(uint4*)a[mt] = *(const uint4*)
                    (sA + (((warp_m * 4 + mt) * 4 + k16) * 32 + lane) * 4);
#pragma unroll
            for (int nt = 0; nt < 4; nt++)
                *(uint2*)b[nt] = *(const uint2*)
                    (sB + (((warp_n * 4 + nt) * 4 + k16) * 32 + lane) * 2);
#pragma unroll
            for (int mt = 0; mt < 4; mt++)
#pragma unroll
                for (int nt = 0; nt < 4; nt++)
                    mma_f16(c[mt][nt], a[mt], b[nt]);
        }
    }

    // epilogue: bias + relu; layer1 -> fp16 store; layer2 -> pool red-add
    int g = lane >> 2, tg = lane & 3;
#pragma unroll
    for (int mt = 0; mt < 4; mt++) {
        int row = row0 + warp_m * 64 + mt * 16 + g;
        int g0 = (do_pool && row < N_NODES) ? batch[row] : 0;
        int g1 = (do_pool && row + 8 < N_NODES) ? batch[row + 8] : 0;
#pragma unroll
        for (int nt = 0; nt < 4; nt++) {
            int col = warp_n * 32 + nt * 8 + tg * 2;
            float b0 = sBias[col], b1 = sBias[col + 1];
            float r0x = fmaxf(c[mt][nt][0] + b0, 0.f);
            float r0y = fmaxf(c[mt][nt][1] + b1, 0.f);
            float r1x = fmaxf(c[mt][nt][2] + b0, 0.f);
            float r1y = fmaxf(c[mt][nt][3] + b1, 0.f);
            if (do_pool) {
                if (row < N_NODES)
                    red_add_v2(g_gsum + (size_t)g0 * 128 + col, r0x, r0y);
                if (row + 8 < N_NODES)
                    red_add_v2(g_gsum + (size_t)g1 * 128 + col, r1x, r1y);
            } else {
                if (row < N_NODES)
                    *(__half2*)(out16 + (size_t)row * 128 + col) = __floats2half2_rn(r0x, r0y);
                if (row + 8 < N_NODES)
                    *(__half2*)(out16 + (size_t)(row + 8) * 128 + col) = __floats2half2_rn(r1x, r1y);
            }
        }
    }
}

// ---------------- final linear head -----------------------------------------
__global__ void k_out(const float* __restrict__ wout, const float* __restrict__ bout,
                      float* __restrict__ y) {
    int g = blockIdx.x;
    __shared__ float row[128];
    float inv = 1.0f / fmaxf(g_gcnt[g], 1.0f);
    row[threadIdx.x] = g_gsum[g * 128 + threadIdx.x] * inv;
    __syncthreads();
    if (threadIdx.x < N_CLS) {
        float s = bout[threadIdx.x];
        const float* wrow = wout + threadIdx.x * 128;
#pragma unroll 16
        for (int d = 0; d < 128; d++) s += row[d] * wrow[d];
        y[g * N_CLS + threadIdx.x] = s;
    }
}

// ---------------- launch -----------------------------------------------------
extern "C" void kernel_launch(void* const* d_in, const int* in_sizes, int n_in,
                              void* d_out, int out_size) {
    const int*   x_tokens = (const int*)  d_in[0];
    const int*   ei       = (const int*)  d_in[1];
    const int*   batch    = (const int*)  d_in[2];
    const float* emb      = (const float*)d_in[3];
    const float* w1l      = (const float*)d_in[4];
    const float* b1       = (const float*)d_in[5];
    const float* w1r      = (const float*)d_in[6];
    const float* w2l      = (const float*)d_in[7];
    const float* b2       = (const float*)d_in[8];
    const float* w2r      = (const float*)d_in[9];
    const float* wout     = (const float*)d_in[10];
    const float* bout     = (const float*)d_in[11];
    float* y = (float*)d_out;

    const int* src = ei;
    const int* dst = ei + N_EDGES;

    cudaFuncSetAttribute(k_mm_mma, cudaFuncAttributeMaxDynamicSharedMemorySize,
                         MM_SMEM);

    __half* p_x16;  cudaGetSymbolAddress((void**)&p_x16, g_x16);
    __half* p_h16;  cudaGetSymbolAddress((void**)&p_h16, g_h16);

    k_zero_pre<<<1024, 256>>>(emb);
    k_embed_counts<<<EMBED_BLOCKS + EDGE4_BLOCKS + NODE4_BLOCKS, 256>>>(x_tokens, dst, batch);
    k_scan   <<<NBLK, 256>>>();
    k_fill   <<<FILL4_BLOCKS, 256>>>(src, dst);

    int mm_grid = (N_NODES + 127) / 128;   // 391
    k_gather <<<(N_NODES * 32 + 255) / 256, 256>>>(0);
    k_mm_mma <<<mm_grid, 256, MM_SMEM>>>(p_x16, w1l, w1r, b1, p_h16, batch, 0);

    k_gather <<<(N_NODES * 32 + 255) / 256, 256>>>(1);
    k_mm_mma <<<mm_grid, 256, MM_SMEM>>>(p_h16, w2l, w2r, b2, nullptr, batch, 1);

    k_out    <<<N_GRAPHS, 128>>>(wout, bout, y);
}

// round 14
// speedup vs baseline: 1.1078x; 1.0553x over previous
#include <cuda_runtime.h>
#include <cuda_fp16.h>
#include <cstdint>

#define N_NODES  50000
#define N_EDGES  600000
#define BAG      16
#define VOCAB    10000
#define EMB      128
#define HID      128
#define N_GRAPHS 512
#define N_CLS    10
#define PAD_IDX  1
#define NBLK 196   // ceil(N_NODES/256)

#define EMBED_BLOCKS ((N_NODES * 32 + 255) / 256)       // 6250
#define EDGE4_BLOCKS ((N_EDGES / 4 + 255) / 256)        // 586
#define NODE4_BLOCKS ((N_NODES / 4 + 255) / 256)        // 49
#define E4_TOTAL     (N_EDGES / 4)                       // 150000
#define E4_PER_BLK   ((E4_TOTAL + NBLK - 1) / NBLK)      // 766

typedef unsigned long long ull;

// ---------------- scratch (static device globals; no allocation) ------------
__device__ __align__(16) __half g_x16 [N_NODES * HID];  // embed out / features
__device__ __align__(16) __half g_h16 [N_NODES * HID];  // layer1 out
__device__ __align__(16) __half g_agg16[N_NODES * HID]; // neighbor mean
__device__ __align__(16) __half g_tab16[VOCAB * EMB];   // fp16 emb table
__device__ __align__(16) __half g_w16[4][HID * HID];    // fp16 wl1,wr1,wl2,wr2
__device__ __align__(16) float g_gsum[N_GRAPHS * HID];
__device__ __align__(16) float g_gcnt[N_GRAPHS];
// CSR
__device__ int g_degi  [N_NODES];
__device__ int g_offs  [N_NODES];
__device__ int g_cursor[N_NODES];
__device__ int g_adj   [N_EDGES];
__device__ ull g_sstate[NBLK];     // decoupled-lookback state
__device__ int g_gbar;             // grid barrier for scan+fill

// ---------------- helpers ----------------------------------------------------
__device__ __forceinline__ void red_add_v2(float* p, float a, float b) {
    asm volatile("red.global.add.v2.f32 [%0], {%1,%2};"
                 :: "l"(p), "f"(a), "f"(b) : "memory");
}
__device__ __forceinline__ void mma_f16(float* c, const uint32_t* a, const uint32_t* b) {
    asm volatile("mma.sync.aligned.m16n8k16.row.col.f32.f16.f16.f32 "
        "{%0,%1,%2,%3}, {%4,%5,%6,%7}, {%8,%9}, {%0,%1,%2,%3};"
        : "+f"(c[0]), "+f"(c[1]), "+f"(c[2]), "+f"(c[3])
        : "r"(a[0]), "r"(a[1]), "r"(a[2]), "r"(a[3]), "r"(b[0]), "r"(b[1]));
}
__device__ __forceinline__ float4 ld_h4(const __half* p) {
    uint2 u = *(const uint2*)p;
    __half2 h0 = *(__half2*)&u.x, h1 = *(__half2*)&u.y;
    float2 f0 = __half22float2(h0), f1 = __half22float2(h1);
    return make_float4(f0.x, f0.y, f1.x, f1.y);
}
__device__ __forceinline__ void st_h4(__half* p, float4 v) {
    uint2 u;
    *(__half2*)&u.x = __floats2half2_rn(v.x, v.y);
    *(__half2*)&u.y = __floats2half2_rn(v.z, v.w);
    *(uint2*)p = u;
}

// ---------------- zeroing + table/weight prep --------------------------------
__global__ void k_zero_pre(const float* __restrict__ table,
                           const float* __restrict__ w1l, const float* __restrict__ w1r,
                           const float* __restrict__ w2l, const float* __restrict__ w2r) {
    int t = blockIdx.x * blockDim.x + threadIdx.x;
    int stride = gridDim.x * blockDim.x;
    if (t == 0) g_gbar = 0;
    for (int i = t; i < N_NODES; i += stride) g_degi[i] = 0;
    for (int i = t; i < N_GRAPHS; i += stride) g_gcnt[i] = 0.f;
    for (int i = t; i < N_GRAPHS * HID; i += stride) g_gsum[i] = 0.f;
    for (int i = t; i < NBLK; i += stride) g_sstate[i] = 0ull;
    for (int i = t; i < VOCAB * EMB / 4; i += stride) {
        float4 v = ((const float4*)table)[i];
        st_h4(g_tab16 + i * 4, v);
    }
    const float* ws[4] = {w1l, w1r, w2l, w2r};
#pragma unroll
    for (int w = 0; w < 4; w++)
        for (int i = t; i < HID * HID / 4; i += stride) {
            float4 v = ((const float4*)ws[w])[i];
            st_h4(g_w16[w] + i * 4, v);
        }
}

// ---------------- embedding bag (mean) + degree/graph counts (merged) -------
__global__ void k_embed_counts(const int* __restrict__ tokens,
                               const int* __restrict__ dst,
                               const int* __restrict__ batch) {
    if (blockIdx.x >= EMBED_BLOCKS) {
        int b = blockIdx.x - EMBED_BLOCKS;
        if (b < EDGE4_BLOCKS) {
            int i = (b * 256 + threadIdx.x) * 4;
            if (i + 4 <= N_EDGES) {
                int4 d4 = *(const int4*)(dst + i);
                atomicAdd(&g_degi[d4.x], 1);
                atomicAdd(&g_degi[d4.y], 1);
                atomicAdd(&g_degi[d4.z], 1);
                atomicAdd(&g_degi[d4.w], 1);
            }
        } else {
            int i = ((b - EDGE4_BLOCKS) * 256 + threadIdx.x) * 4;
            if (i + 4 <= N_NODES) {
                int4 b4 = *(const int4*)(batch + i);
                atomicAdd(&g_gcnt[b4.x], 1.0f);
                atomicAdd(&g_gcnt[b4.y], 1.0f);
                atomicAdd(&g_gcnt[b4.z], 1.0f);
                atomicAdd(&g_gcnt[b4.w], 1.0f);
            }
        }
        return;
    }
    int w = (blockIdx.x * blockDim.x + threadIdx.x) >> 5;
    int lane = threadIdx.x & 31;
    if (w >= N_NODES) return;
    const int* tk = tokens + w * BAG;
    float4 acc = make_float4(0.f, 0.f, 0.f, 0.f);
    int cnt = 0;
#pragma unroll
    for (int t = 0; t < BAG; t++) {
        int tok = tk[t];
        if (tok != PAD_IDX) {
            cnt++;
            float4 e = ld_h4(g_tab16 + (size_t)tok * EMB + lane * 4);
            acc.x += e.x; acc.y += e.y; acc.z += e.z; acc.w += e.w;
        }
    }
    float inv = 1.0f / (float)max(cnt, 1);
    acc.x *= inv; acc.y *= inv; acc.z *= inv; acc.w *= inv;
    st_h4(g_x16 + (size_t)w * HID + lane * 4, acc);
}

// ---------------- scan (decoupled lookback) + CSR fill, one kernel ----------
__global__ void k_scan_fill(const int* __restrict__ src, const int* __restrict__ dst) {
    __shared__ int wsum[8];
    __shared__ ull run_sh;
    int t = threadIdx.x, bid = blockIdx.x;
    int lane = t & 31, wrp = t >> 5;
    int i = bid * 256 + t;
    int v = (i < N_NODES) ? g_degi[i] : 0;
    int sc = v;
#pragma unroll
    for (int o = 1; o < 32; o <<= 1) {
        int x = __shfl_up_sync(0xffffffffu, sc, o);
        if (lane >= o) sc += x;
    }
    if (lane == 31) wsum[wrp] = sc;
    __syncthreads();
    int wbase = 0, total;
    {
        int ws = (lane < 8) ? wsum[lane] : 0;
#pragma unroll
        for (int o = 1; o < 8; o <<= 1) {
            int x = __shfl_up_sync(0xffffffffu, ws, o);
            if (lane >= o) ws += x;
        }
        total  = __shfl_sync(0xffffffffu, ws, 7);
        int wb = __shfl_sync(0xffffffffu, ws, wrp);
        wbase  = wb - wsum[wrp];
    }
    int incl = wbase + sc;
    if (t == 0) {
        ull st = ((ull)(bid == 0 ? 2 : 1) << 32) | (unsigned)total;
        atomicExch(&g_sstate[bid], st);
    }
    if (t < 32) {
        ull run = 0;
        if (bid > 0) {
            int look = bid - 1;
            while (true) {
                int j = look - t;
                ull val; int stt;
                if (j >= 0) {
                    do { val = atomicAdd(&g_sstate[j], 0ull); stt = (int)(val >> 32); }
                    while (stt == 0);
                } else { val = (2ull << 32); stt = 2; }
                unsigned m = __ballot_sync(0xffffffffu, stt == 2);
                ull contrib;
                if (m) {
                    int first = __ffs(m) - 1;
                    contrib = (t <= first) ? (val & 0xffffffffull) : 0ull;
                } else {
                    contrib = val & 0xffffffffull;
                }
#pragma unroll
                for (int off = 16; off; off >>= 1)
                    contrib += __shfl_down_sync(0xffffffffu, contrib, off);
                contrib = __shfl_sync(0xffffffffu, contrib, 0);
                run += contrib;
                if (m) break;
                look -= 32;
            }
        }
        if (t == 0) {
            run_sh = run;
            if (bid > 0)
                atomicExch(&g_sstate[bid],
                           (2ull << 32) | (unsigned)(run + (ull)total));
        }
    }
    __syncthreads();
    if (i < N_NODES) {
        int off = (int)run_sh + incl - v;
        g_offs[i] = off;
        g_cursor[i] = off;
    }

    // ---- grid barrier: all cursors written before any fill atomics ----
    __threadfence();
    __syncthreads();
    if (t == 0) {
        atomicAdd(&g_gbar, 1);
        while (atomicAdd(&g_gbar, 0) < NBLK) { }
    }
    __syncthreads();

    // ---- fill phase: this block's contiguous range of int4 edge groups ----
    int g0 = bid * E4_PER_BLK;
    int g1 = min(g0 + E4_PER_BLK, E4_TOTAL);
    for (int g = g0 + t; g < g1; g += 256) {
        int e = g * 4;
        int4 s4 = *(const int4*)(src + e);
        int4 d4 = *(const int4*)(dst + e);
        int p0 = atomicAdd(&g_cursor[d4.x], 1);
        int p1 = atomicAdd(&g_cursor[d4.y], 1);
        int p2 = atomicAdd(&g_cursor[d4.z], 1);
        int p3 = atomicAdd(&g_cursor[d4.w], 1);
        g_adj[p0] = s4.x;
        g_adj[p1] = s4.y;
        g_adj[p2] = s4.z;
        g_adj[p3] = s4.w;
    }
}

// ---------------- gather aggregation: agg[n] = mean_{s in N(n)} x[s] --------
__global__ void k_gather(int phase) {
    const __half* __restrict__ x = phase ? g_h16 : g_x16;
    int w = (blockIdx.x * blockDim.x + threadIdx.x) >> 5;
    int lane = threadIdx.x & 31;
    if (w >= N_NODES) return;
    int beg = g_offs[w];
    int d   = g_degi[w];
    float4 acc0 = make_float4(0.f, 0.f, 0.f, 0.f);
    float4 acc1 = make_float4(0.f, 0.f, 0.f, 0.f);
    int i = 0;
    for (; i + 2 <= d; i += 2) {
        int s0 = g_adj[beg + i], s1 = g_adj[beg + i + 1];
        float4 v0 = ld_h4(x + (size_t)s0 * HID + lane * 4);
        float4 v1 = ld_h4(x + (size_t)s1 * HID + lane * 4);
        acc0.x += v0.x; acc0.y += v0.y; acc0.z += v0.z; acc0.w += v0.w;
        acc1.x += v1.x; acc1.y += v1.y; acc1.z += v1.z; acc1.w += v1.w;
    }
    if (i < d) {
        int s0 = g_adj[beg + i];
        float4 v0 = ld_h4(x + (size_t)s0 * HID + lane * 4);
        acc0.x += v0.x; acc0.y += v0.y; acc0.z += v0.z; acc0.w += v0.w;
    }
    float inv = 1.0f / (float)max(d, 1);
    float4 o;
    o.x = (acc0.x + acc1.x) * inv;
    o.y = (acc0.y + acc1.y) * inv;
    o.z = (acc0.z + acc1.z) * inv;
    o.w = (acc0.w + acc1.w) * inv;
    st_h4(g_agg16 + (size_t)w * HID + lane * 4, o);
}

// ---------------- fp16 mma.sync fused dual GEMM + bias + relu (+pool) -------
// out = relu( [agg | xin] @ [wl | wr]^T + bias ), K=256, 128x128 CTA tile
#define MM_SMEM (32768 + 512)

__global__ __launch_bounds__(256) void k_mm_mma(const __half* __restrict__ xin,
                                                const __half* __restrict__ wl16,
                                                const __half* __restrict__ wr16,
                                                const float* __restrict__ bias,
                                                __half* __restrict__ out16,
                                                const int* __restrict__ batch,
                                                int do_pool) {
    extern __shared__ uint32_t smu[];
    uint32_t* sA = smu;                 // 4096 u32
    uint32_t* sB = smu + 4096;          // 4096 u32
    float* sBias = (float*)(smu + 8192);
    int tid = threadIdx.x;
    int lane = tid & 31, wid = tid >> 5;
    int warp_m = wid & 1;           // 2 warps over M (64 rows each)
    int warp_n = wid >> 1;          // 4 warps over N (32 cols each)
    int row0 = blockIdx.x * 128;
    if (tid < 128) sBias[tid] = bias[tid];

    float c[4][4][4];
#pragma unroll
    for (int mt = 0; mt < 4; mt++)
#pragma unroll
        for (int nt = 0; nt < 4; nt++)
#pragma unroll
            for (int r = 0; r < 4; r++) c[mt][nt][r] = 0.f;

    for (int ch = 0; ch < 4; ch++) {
        const __half* srcA = ((ch < 2) ? g_agg16 : xin) + (ch & 1) * 64;
        const __half* srcW = (ch < 2) ? wl16 : wr16;
        int kw = (ch & 1) * 64;
        __syncthreads();
        // A tile: 128 rows x 64 k fp16 -> fragment-order smem (16B loads)
#pragma unroll
        for (int i = 0; i < 4; i++) {
            int idx = tid + i * 256;         // 0..1023
            int r = idx >> 3, q = idx & 7;   // row, 8-half group
            int rg = row0 + r;
            uint4 u = make_uint4(0u, 0u, 0u, 0u);
            if (rg < N_NODES)
                u = *(const uint4*)(srcA + (size_t)rg * 128 + q * 8);
            int mt = r >> 4, ri = r & 15;
            int k16 = q >> 1;
            int reg = (ri >= 8 ? 1 : 0) + 2 * (q & 1);
            uint32_t base = ((mt * 4 + k16) * 32) * 4 + reg;
            uint32_t lb = (ri & 7) * 16;     // lane*4 in u32 units
            sA[base + lb +  0] = u.x;
            sA[base + lb +  4] = u.y;
            sA[base + lb +  8] = u.z;
            sA[base + lb + 12] = u.w;
        }
        // B tile: w16[n][k] fp16 -> fragment-order smem (16B loads)
#pragma unroll
        for (int i = 0; i < 4; i++) {
            int idx = tid + i * 256;         // 0..1023
            int n = idx >> 3, q8 = idx & 7;  // out-col, 8-half group
            uint4 u = *(const uint4*)(srcW + (size_t)n * 128 + kw + q8 * 8);
            int nt = n >> 3;
            int k16 = q8 >> 1, reg = q8 & 1;
            uint32_t base = ((nt * 4 + k16) * 32 + (n & 7) * 4) * 2 + reg;
            sB[base + 0] = u.x;
            sB[base + 2] = u.y;
            sB[base + 4] = u.z;
            sB[base + 6] = u.w;
        }
        __syncthreads();
#pragma unroll
        for (int k16 = 0; k16 < 4; k16++) {
            uint32_t a[4][4], b[4][2];
#pragma unroll
            for (int mt = 0; mt < 4; mt++)
                *(uint4*)a[mt] = *(const uint4*)
                    (sA + (((warp_m * 4 + mt) * 4 + k16) * 32 + lane) * 4);
#pragma unroll
            for (int nt = 0; nt < 4; nt++)
                *(uint2*)b[nt] = *(const uint2*)
                    (sB + (((warp_n * 4 + nt) * 4 + k16) * 32 + lane) * 2);
#pragma unroll
            for (int mt = 0; mt < 4; mt++)
#pragma unroll
                for (int nt = 0; nt < 4; nt++)
                    mma_f16(c[mt][nt], a[mt], b[nt]);
        }
    }

    // epilogue: bias + relu; layer1 -> fp16 store; layer2 -> pool red-add
    int g = lane >> 2, tg = lane & 3;
#pragma unroll
    for (int mt = 0; mt < 4; mt++) {
        int row = row0 + warp_m * 64 + mt * 16 + g;
        int g0 = (do_pool && row < N_NODES) ? batch[row] : 0;
        int g1 = (do_pool && row + 8 < N_NODES) ? batch[row + 8] : 0;
#pragma unroll
        for (int nt = 0; nt < 4; nt++) {
            int col = warp_n * 32 + nt * 8 + tg * 2;
            float b0 = sBias[col], b1 = sBias[col + 1];
            float r0x = fmaxf(c[mt][nt][0] + b0, 0.f);
            float r0y = fmaxf(c[mt][nt][1] + b1, 0.f);
            float r1x = fmaxf(c[mt][nt][2] + b0, 0.f);
            float r1y = fmaxf(c[mt][nt][3] + b1, 0.f);
            if (do_pool) {
                if (row < N_NODES)
                    red_add_v2(g_gsum + (size_t)g0 * 128 + col, r0x, r0y);
                if (row + 8 < N_NODES)
                    red_add_v2(g_gsum + (size_t)g1 * 128 + col, r1x, r1y);
            } else {
                if (row < N_NODES)
                    *(__half2*)(out16 + (size_t)row * 128 + col) = __floats2half2_rn(r0x, r0y);
                if (row + 8 < N_NODES)
                    *(__half2*)(out16 + (size_t)(row + 8) * 128 + col) = __floats2half2_rn(r1x, r1y);
            }
        }
    }
}

// ---------------- final linear head -----------------------------------------
__global__ void k_out(const float* __restrict__ wout, const float* __restrict__ bout,
                      float* __restrict__ y) {
    int g = blockIdx.x;
    __shared__ float row[128];
    float inv = 1.0f / fmaxf(g_gcnt[g], 1.0f);
    row[threadIdx.x] = g_gsum[g * 128 + threadIdx.x] * inv;
    __syncthreads();
    if (threadIdx.x < N_CLS) {
        float s = bout[threadIdx.x];
        const float* wrow = wout + threadIdx.x * 128;
#pragma unroll 16
        for (int d = 0; d < 128; d++) s += row[d] * wrow[d];
        y[g * N_CLS + threadIdx.x] = s;
    }
}

// ---------------- launch -----------------------------------------------------
extern "C" void kernel_launch(void* const* d_in, const int* in_sizes, int n_in,
                              void* d_out, int out_size) {
    const int*   x_tokens = (const int*)  d_in[0];
    const int*   ei       = (const int*)  d_in[1];
    const int*   batch    = (const int*)  d_in[2];
    const float* emb      = (const float*)d_in[3];
    const float* w1l      = (const float*)d_in[4];
    const float* b1       = (const float*)d_in[5];
    const float* w1r      = (const float*)d_in[6];
    const float* w2l      = (const float*)d_in[7];
    const float* b2       = (const float*)d_in[8];
    const float* w2r      = (const float*)d_in[9];
    const float* wout     = (const float*)d_in[10];
    const float* bout     = (const float*)d_in[11];
    float* y = (float*)d_out;

    const int* src = ei;
    const int* dst = ei + N_EDGES;

    cudaFuncSetAttribute(k_mm_mma, cudaFuncAttributeMaxDynamicSharedMemorySize,
                         MM_SMEM);

    __half* p_x16;  cudaGetSymbolAddress((void**)&p_x16, g_x16);
    __half* p_h16;  cudaGetSymbolAddress((void**)&p_h16, g_h16);
    __half* p_w16;  cudaGetSymbolAddress((void**)&p_w16, g_w16);

    k_zero_pre<<<1024, 256>>>(emb, w1l, w1r, w2l, w2r);
    k_embed_counts<<<EMBED_BLOCKS + EDGE4_BLOCKS + NODE4_BLOCKS, 256>>>(x_tokens, dst, batch);
    k_scan_fill<<<NBLK, 256>>>(src, dst);

    int mm_grid = (N_NODES + 127) / 128;   // 391
    k_gather <<<(N_NODES * 32 + 255) / 256, 256>>>(0);
    k_mm_mma <<<mm_grid, 256, MM_SMEM>>>(p_x16, p_w16, p_w16 + HID * HID,
                                         b1, p_h16, batch, 0);

    k_gather <<<(N_NODES * 32 + 255) / 256, 256>>>(1);
    k_mm_mma <<<mm_grid, 256, MM_SMEM>>>(p_h16, p_w16 + 2 * HID * HID,
                                         p_w16 + 3 * HID * HID, b2, nullptr, batch, 1);

    k_out    <<<N_GRAPHS, 128>>>(wout, bout, y);
}